// round 1
// baseline (speedup 1.0000x reference)
#include <cuda_runtime.h>
#include <cuda_bf16.h>
#include <cstdint>
#include <cstddef>

// ---------------------------------------------------------------------------
// Problem constants
// ---------------------------------------------------------------------------
#define BATCH     4096
#define IN_DIM    10000
#define H1        512
#define H2        256
#define NPRIM     32
#define PDIM      8
#define NLAB      100
#define CDIM      16
#define JO        (NLAB*CDIM)          // 1600
#define PREDS_PER_B (NPRIM*JO)         // 51200

// ---------------------------------------------------------------------------
// Scratch (static device arrays; no runtime allocation)
// ---------------------------------------------------------------------------
__device__ float g_x1   [(size_t)BATCH*H1];          // 8 MB
__device__ float g_x2   [(size_t)BATCH*H2];          // 4 MB
__device__ float g_p    [(size_t)BATCH*H2];          // 4 MB  (primary caps, post-LN)
__device__ float g_WpT  [H2*H2];                     // 256 KB
__device__ float g_preds[(size_t)BATCH*PREDS_PER_B]; // 839 MB
__device__ float g_v    [(size_t)BATCH*JO];          // 26 MB

// ---------------------------------------------------------------------------
// Generic fp32 tiled GEMM:  C[M,N] = act(A[M,K] @ B[K,N] + bias[N])
// M divisible by BM, K divisible by BK. N guarded.
// ---------------------------------------------------------------------------
template<int BM,int BN,int BK,int TM,int TN,bool RELU>
__global__ __launch_bounds__((BM/TM)*(BN/TN))
void sgemm_kernel(const float* __restrict__ A, const float* __restrict__ B,
                  const float* __restrict__ bias, float* __restrict__ C,
                  int M, int N, int K)
{
    constexpr int THREADS = (BM/TM)*(BN/TN);
    __shared__ float As[BK][BM];
    __shared__ float Bs[BK][BN];

    const int tid = threadIdx.x;
    const int bm  = blockIdx.y * BM;
    const int bn  = blockIdx.x * BN;
    const int tc  = tid % (BN/TN);
    const int tr  = tid / (BN/TN);

    float acc[TM][TN];
    #pragma unroll
    for (int i=0;i<TM;i++)
        #pragma unroll
        for (int j=0;j<TN;j++) acc[i][j] = 0.f;

    constexpr int A_LOADS = BM*BK/THREADS;
    constexpr int B_LOADS = BK*BN/THREADS;

    for (int k0 = 0; k0 < K; k0 += BK) {
        #pragma unroll
        for (int l=0;l<A_LOADS;l++){
            int idx = tid + l*THREADS;
            int m = idx / BK, kk = idx % BK;
            As[kk][m] = A[(size_t)(bm+m)*K + k0 + kk];
        }
        #pragma unroll
        for (int l=0;l<B_LOADS;l++){
            int idx = tid + l*THREADS;
            int kk = idx / BN, n = idx % BN;
            int gn = bn + n;
            Bs[kk][n] = (gn < N) ? B[(size_t)(k0+kk)*N + gn] : 0.f;
        }
        __syncthreads();
        #pragma unroll
        for (int kk=0; kk<BK; kk++){
            float a[TM], b[TN];
            #pragma unroll
            for (int i=0;i<TM;i++) a[i] = As[kk][tr*TM+i];
            #pragma unroll
            for (int j=0;j<TN;j++) b[j] = Bs[kk][tc*TN+j];
            #pragma unroll
            for (int i=0;i<TM;i++)
                #pragma unroll
                for (int j=0;j<TN;j++)
                    acc[i][j] += a[i]*b[j];
        }
        __syncthreads();
    }

    #pragma unroll
    for (int i=0;i<TM;i++){
        int gm = bm + tr*TM + i;
        #pragma unroll
        for (int j=0;j<TN;j++){
            int gn = bn + tc*TN + j;
            if (gn < N){
                float v = acc[i][j] + bias[gn];
                if (RELU) v = fmaxf(v, 0.f);
                C[(size_t)gm*N + gn] = v;
            }
        }
    }
}

// ---------------------------------------------------------------------------
// Transpose Wp[n][i][o] (32,256,8) -> WpT[i][n*8+o] (256,256)
// ---------------------------------------------------------------------------
__global__ void transpose_wp_kernel(const float* __restrict__ Wp, float* __restrict__ WpT)
{
    int idx = blockIdx.x*256 + threadIdx.x;        // 65536 total
    int n = idx >> 11;
    int r = idx & 2047;
    int i = r >> 3;
    int o = r & 7;
    WpT[i*H2 + n*8 + o] = Wp[idx];
}

// ---------------------------------------------------------------------------
// Per-capsule LayerNorm over the 8-dim, in place on g_p.
// One thread per (b, n) group.
// ---------------------------------------------------------------------------
__global__ __launch_bounds__(256)
void ln_kernel(float* __restrict__ p, const float* __restrict__ g, const float* __restrict__ bb)
{
    int gid = blockIdx.x*256 + threadIdx.x;        // BATCH*NPRIM = 131072
    int n = gid & (NPRIM-1);
    size_t base = (size_t)gid * PDIM;

    float x[PDIM];
    #pragma unroll
    for (int i=0;i<PDIM;i++) x[i] = p[base+i];

    float mu = 0.f;
    #pragma unroll
    for (int i=0;i<PDIM;i++) mu += x[i];
    mu *= (1.f/PDIM);
    float var = 0.f;
    #pragma unroll
    for (int i=0;i<PDIM;i++){ float d = x[i]-mu; var += d*d; }
    var *= (1.f/PDIM);
    float rs = rsqrtf(var + 1e-5f);

    int c0 = n*PDIM;
    #pragma unroll
    for (int i=0;i<PDIM;i++)
        p[base+i] = (x[i]-mu)*rs*g[c0+i] + bb[c0+i];
}

// ---------------------------------------------------------------------------
// preds[b,n,j,o] = sum_i p[b,n,i] * Wr[n,j,o,i]
// Grid: (BATCH/128, NPRIM). Each thread owns up to 7 jo rows of Wr (registers),
// loops over the 128-row batch tile -> Wr read once per 128 batch rows.
// ---------------------------------------------------------------------------
__global__ __launch_bounds__(256)
void preds_kernel(const float* __restrict__ p, const float* __restrict__ Wr,
                  float* __restrict__ preds)
{
    __shared__ float ps[128*PDIM];
    const int n   = blockIdx.y;
    const int b0  = blockIdx.x * 128;
    const int tid = threadIdx.x;

    for (int t = tid; t < 128*PDIM; t += 256){
        int bl = t >> 3, i = t & 7;
        ps[t] = p[(size_t)(b0+bl)*H2 + n*PDIM + i];
    }
    __syncthreads();

    float wr[7][8];
    #pragma unroll
    for (int q=0;q<7;q++){
        int jo = tid + q*256;
        if (jo < JO){
            const float4* w = (const float4*)(Wr + (size_t)n*(JO*PDIM) + (size_t)jo*PDIM);
            float4 lo = w[0], hi = w[1];
            wr[q][0]=lo.x; wr[q][1]=lo.y; wr[q][2]=lo.z; wr[q][3]=lo.w;
            wr[q][4]=hi.x; wr[q][5]=hi.y; wr[q][6]=hi.z; wr[q][7]=hi.w;
        }
    }

    for (int bl=0; bl<128; bl++){
        float p8[8];
        #pragma unroll
        for (int i=0;i<8;i++) p8[i] = ps[bl*8 + i];
        float* outrow = preds + (size_t)(b0+bl)*PREDS_PER_B + (size_t)n*JO;
        #pragma unroll
        for (int q=0;q<7;q++){
            int jo = tid + q*256;
            if (jo < JO){
                float a = 0.f;
                #pragma unroll
                for (int i=0;i<8;i++) a += p8[i]*wr[q][i];
                outrow[jo] = a;
            }
        }
    }
}

// ---------------------------------------------------------------------------
// Dynamic routing: one block per batch element, all 3 iterations local.
// smem: preds (51200 f32) | b_logit (3200) | s/v (1600) | m,zinv (64) | cbuf (256)
// ---------------------------------------------------------------------------
#define RT_SMEM_FLOATS (PREDS_PER_B + NPRIM*NLAB + JO + 64 + 256)
#define RT_SMEM_BYTES  (RT_SMEM_FLOATS*4)

__global__ __launch_bounds__(256)
void routing_kernel(const float* __restrict__ preds_g, float* __restrict__ v_out)
{
    extern __shared__ float sraw[];
    float* preds_s = sraw;                       // 51200
    float* blog    = preds_s + PREDS_PER_B;      // 3200
    float* sv      = blog + NPRIM*NLAB;          // 1600
    float* mz      = sv + JO;                    // 64: m[32], zinv[32]
    float* cbuf    = mz + 64;                    // 2 x 128

    const int tid  = threadIdx.x;
    const int b    = blockIdx.x;
    const int wid  = tid >> 5;
    const int lane = tid & 31;

    // stage preds[b] into smem (vectorized)
    {
        const float4* pg = (const float4*)(preds_g + (size_t)b*PREDS_PER_B);
        float4* pd = (float4*)preds_s;
        for (int t = tid; t < PREDS_PER_B/4; t += 256) pd[t] = pg[t];
    }
    for (int t = tid; t < NPRIM*NLAB; t += 256) blog[t] = 0.f;
    __syncthreads();

    for (int it = 0; it < 3; it++){
        // --- softmax stats per capsule n (8 warps x 4 capsules) ---
        #pragma unroll
        for (int nn = 0; nn < 4; nn++){
            int n = wid*4 + nn;
            const float* row = blog + n*NLAB;
            float x0 = row[lane];
            float x1 = row[lane+32];
            float x2 = row[lane+64];
            float x3 = (lane < 4) ? row[lane+96] : -1e30f;
            float m = fmaxf(fmaxf(x0,x1), fmaxf(x2,x3));
            #pragma unroll
            for (int off=16; off>=1; off>>=1) m = fmaxf(m, __shfl_xor_sync(0xffffffffu, m, off));
            float z = expf(x0-m) + expf(x1-m) + expf(x2-m) + ((lane<4)?expf(x3-m):0.f);
            #pragma unroll
            for (int off=16; off>=1; off>>=1) z += __shfl_xor_sync(0xffffffffu, z, off);
            if (lane == 0){ mz[n] = m; mz[32+n] = 1.f/z; }
        }
        __syncthreads();

        // --- s[j,o] = sum_n c[n,j]*preds[n,j,o], n-outer with c row staged ---
        float acc[7];
        #pragma unroll
        for (int t=0;t<7;t++) acc[t] = 0.f;

        for (int n = 0; n < NPRIM; n++){
            float* crow = cbuf + (n & 1)*128;
            if (tid < NLAB)
                crow[tid] = expf(blog[n*NLAB + tid] - mz[n]) * mz[32+n];
            __syncthreads();
            const float* pn = preds_s + n*JO;
            #pragma unroll
            for (int t=0;t<7;t++){
                int idx = tid + t*256;
                if (idx < JO) acc[t] += crow[idx>>4] * pn[idx];
            }
        }
        __syncthreads();
        #pragma unroll
        for (int t=0;t<7;t++){
            int idx = tid + t*256;
            if (idx < JO) sv[idx] = acc[t];
        }
        __syncthreads();

        // --- squash per label j ---
        if (tid < NLAB){
            float sq = 0.f;
            #pragma unroll
            for (int o=0;o<CDIM;o++){ float x = sv[tid*CDIM+o]; sq += x*x; }
            float scale = sq / ((1.f + sq) * sqrtf(sq + 1e-8f));
            #pragma unroll
            for (int o=0;o<CDIM;o++) sv[tid*CDIM+o] *= scale;
        }
        __syncthreads();

        if (it < 2){
            // --- agreement: b_logit[n,j] += sum_o preds[n,j,o]*v[j,o] ---
            #pragma unroll
            for (int t=0;t<13;t++){
                int idx = tid + t*256;
                if (idx < NPRIM*NLAB){
                    int n = idx / NLAB, j = idx % NLAB;
                    const float* pr = preds_s + n*JO + j*CDIM;
                    const float* vv = sv + j*CDIM;
                    float a = 0.f;
                    #pragma unroll
                    for (int o=0;o<CDIM;o++) a += pr[o]*vv[o];
                    blog[idx] += a;
                }
            }
            __syncthreads();
        } else {
            #pragma unroll
            for (int t=0;t<7;t++){
                int idx = tid + t*256;
                if (idx < JO) v_out[(size_t)b*JO + idx] = sv[idx];
            }
        }
    }
}

// ---------------------------------------------------------------------------
// Launch
// ---------------------------------------------------------------------------
extern "C" void kernel_launch(void* const* d_in, const int* in_sizes, int n_in,
                              void* d_out, int out_size)
{
    const float* features = (const float*)d_in[0];
    const float* W1 = (const float*)d_in[1];
    const float* b1 = (const float*)d_in[2];
    const float* W2 = (const float*)d_in[3];
    const float* b2 = (const float*)d_in[4];
    const float* Wp = (const float*)d_in[5];
    const float* bp = (const float*)d_in[6];
    const float* lg = (const float*)d_in[7];
    const float* lb = (const float*)d_in[8];
    const float* Wr = (const float*)d_in[9];
    const float* Wc = (const float*)d_in[10];
    const float* bc = (const float*)d_in[11];
    float* out = (float*)d_out;

    void *px1, *px2, *pp, *pwpt, *ppreds, *pv;
    cudaGetSymbolAddress(&px1, g_x1);
    cudaGetSymbolAddress(&px2, g_x2);
    cudaGetSymbolAddress(&pp, g_p);
    cudaGetSymbolAddress(&pwpt, g_WpT);
    cudaGetSymbolAddress(&ppreds, g_preds);
    cudaGetSymbolAddress(&pv, g_v);
    float* x1 = (float*)px1;
    float* x2 = (float*)px2;
    float* p  = (float*)pp;
    float* WpT = (float*)pwpt;
    float* preds = (float*)ppreds;
    float* v = (float*)pv;

    cudaFuncSetAttribute(routing_kernel,
                         cudaFuncAttributeMaxDynamicSharedMemorySize, RT_SMEM_BYTES);

    // 1) x1 = relu(features @ W1 + b1)     [4096,512]
    sgemm_kernel<128,128,8,8,8,true><<<dim3(H1/128, BATCH/128), 256>>>(
        features, W1, b1, x1, BATCH, H1, IN_DIM);

    // 2) x2 = relu(x1 @ W2 + b2)           [4096,256]
    sgemm_kernel<128,128,8,8,8,true><<<dim3(H2/128, BATCH/128), 256>>>(
        x1, W2, b2, x2, BATCH, H2, H1);

    // 3) WpT = transpose(Wp)
    transpose_wp_kernel<<<NPRIM*H2*PDIM/256, 256>>>(Wp, WpT);

    // 4) p = x2 @ WpT + bp                 [4096,256]
    sgemm_kernel<128,128,8,8,8,false><<<dim3(H2/128, BATCH/128), 256>>>(
        x2, WpT, bp, p, BATCH, H2, H2);

    // 5) per-capsule LayerNorm (in place)
    ln_kernel<<<BATCH*NPRIM/256, 256>>>(p, lg, lb);

    // 6) preds einsum
    preds_kernel<<<dim3(BATCH/128, NPRIM), 256>>>(p, Wr, preds);

    // 7) dynamic routing (3 iters, block-local) -> v
    routing_kernel<<<BATCH, 256, RT_SMEM_BYTES>>>(preds, v);

    // 8) logits = v.reshape(B,1600) @ Wc + bc
    sgemm_kernel<32,128,8,2,8,false><<<dim3(1, BATCH/32), 256>>>(
        v, Wc, bc, out, BATCH, NLAB, JO);
}

// round 2
// speedup vs baseline: 1.8408x; 1.8408x over previous
#include <cuda_runtime.h>
#include <cuda_bf16.h>
#include <cstdint>
#include <cstddef>

// ---------------------------------------------------------------------------
// Problem constants
// ---------------------------------------------------------------------------
#define BATCH     4096
#define IN_DIM    10000
#define H1        512
#define H2        256
#define NPRIM     32
#define PDIM      8
#define NLAB      100
#define CDIM      16
#define JO        (NLAB*CDIM)          // 1600
#define PREDS_PER_B (NPRIM*JO)         // 51200

// ---------------------------------------------------------------------------
// Scratch (static device arrays; no runtime allocation)
// ---------------------------------------------------------------------------
__device__ float g_x1   [(size_t)BATCH*H1];          // 8 MB
__device__ float g_x2   [(size_t)BATCH*H2];          // 4 MB
__device__ float g_p    [(size_t)BATCH*H2];          // 4 MB
__device__ float g_WpT  [H2*H2];                     // 256 KB
__device__ float g_preds[(size_t)BATCH*PREDS_PER_B]; // 839 MB
__device__ float g_v    [(size_t)BATCH*JO];          // 26 MB

// ---------------------------------------------------------------------------
// TF32 tensor-core GEMM: C[M,N] = act(A[M,K] @ B[K,N] + bias[N])
// BM=128, BN=64, BK=16, 256 threads, 3-stage cp.async pipeline.
// Requires: M%128==0, N%64==0, K%16==0.
// ---------------------------------------------------------------------------
__device__ __forceinline__ uint32_t f2tf32(float x){
    uint32_t u;
    asm("cvt.rna.tf32.f32 %0, %1;" : "=r"(u) : "f"(x));
    return u;
}

template<bool RELU>
__global__ __launch_bounds__(256)
void tf32gemm_kernel(const float* __restrict__ A, const float* __restrict__ B,
                     const float* __restrict__ bias, float* __restrict__ C,
                     int M, int N, int K)
{
    __shared__ float As[3][128][20];   // [stage][m][k] pad->conflict-free frag loads
    __shared__ float Bs[3][16][72];    // [stage][k][n] pad 8 -> conflict-free

    const int tid  = threadIdx.x;
    const int bm   = blockIdx.y * 128;
    const int bn   = blockIdx.x * 64;
    const int wid  = tid >> 5;
    const int lane = tid & 31;
    const int gp   = lane >> 2;     // 0..7
    const int tq   = lane & 3;      // 0..3
    const int warp_m = (wid & 3) * 32;
    const int warp_n = (wid >> 2) * 32;

    // staging indices
    const int a_row = tid >> 2;          // 0..63 (plus +64 for second load)
    const int a_col = (tid & 3) * 4;
    const int b_row = tid >> 4;          // 0..15
    const int b_col = (tid & 15) * 4;

    float acc[2][4][4];
    #pragma unroll
    for (int i=0;i<2;i++)
        #pragma unroll
        for (int j=0;j<4;j++)
            #pragma unroll
            for (int r=0;r<4;r++) acc[i][j][r] = 0.f;

    const int ntiles = K >> 4;

    auto prefetch = [&](int t){
        const int s  = t % 3;
        const int k0 = t << 4;
        {
            uint32_t d0 = (uint32_t)__cvta_generic_to_shared(&As[s][a_row][a_col]);
            const float* g0 = A + (size_t)(bm + a_row) * K + k0 + a_col;
            asm volatile("cp.async.cg.shared.global [%0], [%1], 16;\n" :: "r"(d0), "l"(g0));
            uint32_t d1 = (uint32_t)__cvta_generic_to_shared(&As[s][a_row+64][a_col]);
            const float* g1 = A + (size_t)(bm + a_row + 64) * K + k0 + a_col;
            asm volatile("cp.async.cg.shared.global [%0], [%1], 16;\n" :: "r"(d1), "l"(g1));
        }
        {
            uint32_t d = (uint32_t)__cvta_generic_to_shared(&Bs[s][b_row][b_col]);
            const float* g = B + (size_t)(k0 + b_row) * N + bn + b_col;
            asm volatile("cp.async.cg.shared.global [%0], [%1], 16;\n" :: "r"(d), "l"(g));
        }
        asm volatile("cp.async.commit_group;\n");
    };

    prefetch(0);
    prefetch(1);

    for (int t = 0; t < ntiles; t++){
        if (t + 1 < ntiles) asm volatile("cp.async.wait_group 1;\n");
        else                asm volatile("cp.async.wait_group 0;\n");
        __syncthreads();

        if (t + 2 < ntiles) prefetch(t + 2);

        const int s = t % 3;
        #pragma unroll
        for (int ks = 0; ks < 2; ks++){
            const int k = ks * 8;
            uint32_t af[2][4], bf[4][2];
            #pragma unroll
            for (int mi = 0; mi < 2; mi++){
                const int rm = warp_m + mi*16;
                af[mi][0] = f2tf32(As[s][rm+gp   ][k+tq  ]);
                af[mi][1] = f2tf32(As[s][rm+gp+8 ][k+tq  ]);
                af[mi][2] = f2tf32(As[s][rm+gp   ][k+tq+4]);
                af[mi][3] = f2tf32(As[s][rm+gp+8 ][k+tq+4]);
            }
            #pragma unroll
            for (int ni = 0; ni < 4; ni++){
                const int cn = warp_n + ni*8;
                bf[ni][0] = f2tf32(Bs[s][k+tq  ][cn+gp]);
                bf[ni][1] = f2tf32(Bs[s][k+tq+4][cn+gp]);
            }
            #pragma unroll
            for (int mi = 0; mi < 2; mi++)
                #pragma unroll
                for (int ni = 0; ni < 4; ni++){
                    asm volatile(
                        "mma.sync.aligned.m16n8k8.row.col.f32.tf32.tf32.f32 "
                        "{%0,%1,%2,%3}, {%4,%5,%6,%7}, {%8,%9}, {%0,%1,%2,%3};\n"
                        : "+f"(acc[mi][ni][0]), "+f"(acc[mi][ni][1]),
                          "+f"(acc[mi][ni][2]), "+f"(acc[mi][ni][3])
                        : "r"(af[mi][0]), "r"(af[mi][1]), "r"(af[mi][2]), "r"(af[mi][3]),
                          "r"(bf[ni][0]), "r"(bf[ni][1]));
                }
        }
        __syncthreads();
    }

    // Epilogue: bias + optional relu
    #pragma unroll
    for (int mi = 0; mi < 2; mi++){
        #pragma unroll
        for (int ni = 0; ni < 4; ni++){
            const int col = bn + warp_n + ni*8 + tq*2;
            const float bz0 = bias[col], bz1 = bias[col+1];
            int r0 = bm + warp_m + mi*16 + gp;
            int r1 = r0 + 8;
            float v0 = acc[mi][ni][0] + bz0;
            float v1 = acc[mi][ni][1] + bz1;
            float v2 = acc[mi][ni][2] + bz0;
            float v3 = acc[mi][ni][3] + bz1;
            if (RELU){
                v0 = fmaxf(v0,0.f); v1 = fmaxf(v1,0.f);
                v2 = fmaxf(v2,0.f); v3 = fmaxf(v3,0.f);
            }
            C[(size_t)r0*N + col]   = v0;
            C[(size_t)r0*N + col+1] = v1;
            C[(size_t)r1*N + col]   = v2;
            C[(size_t)r1*N + col+1] = v3;
        }
    }
}

// ---------------------------------------------------------------------------
// Generic fp32 tiled GEMM (kept for the final logits GEMM; N guarded)
// ---------------------------------------------------------------------------
template<int BM,int BN,int BK,int TM,int TN,bool RELU>
__global__ __launch_bounds__((BM/TM)*(BN/TN))
void sgemm_kernel(const float* __restrict__ A, const float* __restrict__ B,
                  const float* __restrict__ bias, float* __restrict__ C,
                  int M, int N, int K)
{
    constexpr int THREADS = (BM/TM)*(BN/TN);
    __shared__ float As[BK][BM];
    __shared__ float Bs[BK][BN];

    const int tid = threadIdx.x;
    const int bm  = blockIdx.y * BM;
    const int bn  = blockIdx.x * BN;
    const int tc  = tid % (BN/TN);
    const int tr  = tid / (BN/TN);

    float acc[TM][TN];
    #pragma unroll
    for (int i=0;i<TM;i++)
        #pragma unroll
        for (int j=0;j<TN;j++) acc[i][j] = 0.f;

    constexpr int A_LOADS = BM*BK/THREADS;
    constexpr int B_LOADS = BK*BN/THREADS;

    for (int k0 = 0; k0 < K; k0 += BK) {
        #pragma unroll
        for (int l=0;l<A_LOADS;l++){
            int idx = tid + l*THREADS;
            int m = idx / BK, kk = idx % BK;
            As[kk][m] = A[(size_t)(bm+m)*K + k0 + kk];
        }
        #pragma unroll
        for (int l=0;l<B_LOADS;l++){
            int idx = tid + l*THREADS;
            int kk = idx / BN, n = idx % BN;
            int gn = bn + n;
            Bs[kk][n] = (gn < N) ? B[(size_t)(k0+kk)*N + gn] : 0.f;
        }
        __syncthreads();
        #pragma unroll
        for (int kk=0; kk<BK; kk++){
            float a[TM], b[TN];
            #pragma unroll
            for (int i=0;i<TM;i++) a[i] = As[kk][tr*TM+i];
            #pragma unroll
            for (int j=0;j<TN;j++) b[j] = Bs[kk][tc*TN+j];
            #pragma unroll
            for (int i=0;i<TM;i++)
                #pragma unroll
                for (int j=0;j<TN;j++)
                    acc[i][j] += a[i]*b[j];
        }
        __syncthreads();
    }

    #pragma unroll
    for (int i=0;i<TM;i++){
        int gm = bm + tr*TM + i;
        #pragma unroll
        for (int j=0;j<TN;j++){
            int gn = bn + tc*TN + j;
            if (gn < N){
                float v = acc[i][j] + bias[gn];
                if (RELU) v = fmaxf(v, 0.f);
                C[(size_t)gm*N + gn] = v;
            }
        }
    }
}

// ---------------------------------------------------------------------------
// Transpose Wp[n][i][o] (32,256,8) -> WpT[i][n*8+o] (256,256)
// ---------------------------------------------------------------------------
__global__ void transpose_wp_kernel(const float* __restrict__ Wp, float* __restrict__ WpT)
{
    int idx = blockIdx.x*256 + threadIdx.x;        // 65536 total
    int n = idx >> 11;
    int r = idx & 2047;
    int i = r >> 3;
    int o = r & 7;
    WpT[i*H2 + n*8 + o] = Wp[idx];
}

// ---------------------------------------------------------------------------
// Per-capsule LayerNorm over the 8-dim, in place on g_p.
// ---------------------------------------------------------------------------
__global__ __launch_bounds__(256)
void ln_kernel(float* __restrict__ p, const float* __restrict__ g, const float* __restrict__ bb)
{
    int gid = blockIdx.x*256 + threadIdx.x;        // BATCH*NPRIM = 131072
    int n = gid & (NPRIM-1);
    size_t base = (size_t)gid * PDIM;

    float x[PDIM];
    #pragma unroll
    for (int i=0;i<PDIM;i++) x[i] = p[base+i];

    float mu = 0.f;
    #pragma unroll
    for (int i=0;i<PDIM;i++) mu += x[i];
    mu *= (1.f/PDIM);
    float var = 0.f;
    #pragma unroll
    for (int i=0;i<PDIM;i++){ float d = x[i]-mu; var += d*d; }
    var *= (1.f/PDIM);
    float rs = rsqrtf(var + 1e-5f);

    int c0 = n*PDIM;
    #pragma unroll
    for (int i=0;i<PDIM;i++)
        p[base+i] = (x[i]-mu)*rs*g[c0+i] + bb[c0+i];
}

// ---------------------------------------------------------------------------
// preds[b,n,j,o] = sum_i p[b,n,i] * Wr[n,j,o,i]
// ---------------------------------------------------------------------------
__global__ __launch_bounds__(256)
void preds_kernel(const float* __restrict__ p, const float* __restrict__ Wr,
                  float* __restrict__ preds)
{
    __shared__ float ps[128*PDIM];
    const int n   = blockIdx.y;
    const int b0  = blockIdx.x * 128;
    const int tid = threadIdx.x;

    for (int t = tid; t < 128*PDIM; t += 256){
        int bl = t >> 3, i = t & 7;
        ps[t] = p[(size_t)(b0+bl)*H2 + n*PDIM + i];
    }
    __syncthreads();

    float wr[7][8];
    #pragma unroll
    for (int q=0;q<7;q++){
        int jo = tid + q*256;
        if (jo < JO){
            const float4* w = (const float4*)(Wr + (size_t)n*(JO*PDIM) + (size_t)jo*PDIM);
            float4 lo = w[0], hi = w[1];
            wr[q][0]=lo.x; wr[q][1]=lo.y; wr[q][2]=lo.z; wr[q][3]=lo.w;
            wr[q][4]=hi.x; wr[q][5]=hi.y; wr[q][6]=hi.z; wr[q][7]=hi.w;
        }
    }

    for (int bl=0; bl<128; bl++){
        float p8[8];
        #pragma unroll
        for (int i=0;i<8;i++) p8[i] = ps[bl*8 + i];
        float* outrow = preds + (size_t)(b0+bl)*PREDS_PER_B + (size_t)n*JO;
        #pragma unroll
        for (int q=0;q<7;q++){
            int jo = tid + q*256;
            if (jo < JO){
                float a = 0.f;
                #pragma unroll
                for (int i=0;i<8;i++) a += p8[i]*wr[q][i];
                outrow[jo] = a;
            }
        }
    }
}

// ---------------------------------------------------------------------------
// Dynamic routing: one block (512 thr) per batch element, 3 iterations local.
// ---------------------------------------------------------------------------
#define RT_SMEM_FLOATS (PREDS_PER_B + NPRIM*NLAB + JO + 64 + 256)
#define RT_SMEM_BYTES  (RT_SMEM_FLOATS*4)

__global__ __launch_bounds__(512)
void routing_kernel(const float* __restrict__ preds_g, float* __restrict__ v_out)
{
    extern __shared__ float sraw[];
    float* preds_s = sraw;                       // 51200
    float* blog    = preds_s + PREDS_PER_B;      // 3200
    float* sv      = blog + NPRIM*NLAB;          // 1600
    float* mz      = sv + JO;                    // 64: m[32], zinv[32]
    float* cbuf    = mz + 64;                    // 2 x 128

    const int tid  = threadIdx.x;
    const int b    = blockIdx.x;
    const int wid  = tid >> 5;
    const int lane = tid & 31;

    // stage preds[b] into smem (vectorized)
    {
        const float4* pg = (const float4*)(preds_g + (size_t)b*PREDS_PER_B);
        float4* pd = (float4*)preds_s;
        for (int t = tid; t < PREDS_PER_B/4; t += 512) pd[t] = pg[t];
    }
    for (int t = tid; t < NPRIM*NLAB; t += 512) blog[t] = 0.f;
    __syncthreads();

    for (int it = 0; it < 3; it++){
        // --- softmax stats per capsule n (16 warps x 2 capsules) ---
        #pragma unroll
        for (int nn = 0; nn < 2; nn++){
            int n = wid*2 + nn;
            const float* row = blog + n*NLAB;
            float x0 = row[lane];
            float x1 = row[lane+32];
            float x2 = row[lane+64];
            float x3 = (lane < 4) ? row[lane+96] : -1e30f;
            float m = fmaxf(fmaxf(x0,x1), fmaxf(x2,x3));
            #pragma unroll
            for (int off=16; off>=1; off>>=1) m = fmaxf(m, __shfl_xor_sync(0xffffffffu, m, off));
            float z = expf(x0-m) + expf(x1-m) + expf(x2-m) + ((lane<4)?expf(x3-m):0.f);
            #pragma unroll
            for (int off=16; off>=1; off>>=1) z += __shfl_xor_sync(0xffffffffu, z, off);
            if (lane == 0){ mz[n] = m; mz[32+n] = 1.f/z; }
        }
        __syncthreads();

        // --- s[j,o] = sum_n c[n,j]*preds[n,j,o] ---
        float acc[4];
        #pragma unroll
        for (int t=0;t<4;t++) acc[t] = 0.f;

        for (int n = 0; n < NPRIM; n++){
            float* crow = cbuf + (n & 1)*128;
            if (tid < NLAB)
                crow[tid] = expf(blog[n*NLAB + tid] - mz[n]) * mz[32+n];
            __syncthreads();
            const float* pn = preds_s + n*JO;
            #pragma unroll
            for (int t=0;t<4;t++){
                int idx = tid + t*512;
                if (idx < JO) acc[t] += crow[idx>>4] * pn[idx];
            }
        }
        __syncthreads();
        #pragma unroll
        for (int t=0;t<4;t++){
            int idx = tid + t*512;
            if (idx < JO) sv[idx] = acc[t];
        }
        __syncthreads();

        // --- squash per label j ---
        if (tid < NLAB){
            float sq = 0.f;
            #pragma unroll
            for (int o=0;o<CDIM;o++){ float x = sv[tid*CDIM+o]; sq += x*x; }
            float scale = sq / ((1.f + sq) * sqrtf(sq + 1e-8f));
            #pragma unroll
            for (int o=0;o<CDIM;o++) sv[tid*CDIM+o] *= scale;
        }
        __syncthreads();

        if (it < 2){
            // --- agreement: b_logit[n,j] += sum_o preds[n,j,o]*v[j,o] ---
            #pragma unroll
            for (int t=0;t<7;t++){
                int idx = tid + t*512;
                if (idx < NPRIM*NLAB){
                    int n = idx / NLAB, j = idx % NLAB;
                    const float* pr = preds_s + n*JO + j*CDIM;
                    const float* vv = sv + j*CDIM;
                    float a = 0.f;
                    #pragma unroll
                    for (int o=0;o<CDIM;o++) a += pr[o]*vv[o];
                    blog[idx] += a;
                }
            }
            __syncthreads();
        } else {
            #pragma unroll
            for (int t=0;t<4;t++){
                int idx = tid + t*512;
                if (idx < JO) v_out[(size_t)b*JO + idx] = sv[idx];
            }
        }
    }
}

// ---------------------------------------------------------------------------
// Launch
// ---------------------------------------------------------------------------
extern "C" void kernel_launch(void* const* d_in, const int* in_sizes, int n_in,
                              void* d_out, int out_size)
{
    const float* features = (const float*)d_in[0];
    const float* W1 = (const float*)d_in[1];
    const float* b1 = (const float*)d_in[2];
    const float* W2 = (const float*)d_in[3];
    const float* b2 = (const float*)d_in[4];
    const float* Wp = (const float*)d_in[5];
    const float* bp = (const float*)d_in[6];
    const float* lg = (const float*)d_in[7];
    const float* lb = (const float*)d_in[8];
    const float* Wr = (const float*)d_in[9];
    const float* Wc = (const float*)d_in[10];
    const float* bc = (const float*)d_in[11];
    float* out = (float*)d_out;

    void *px1, *px2, *pp, *pwpt, *ppreds, *pv;
    cudaGetSymbolAddress(&px1, g_x1);
    cudaGetSymbolAddress(&px2, g_x2);
    cudaGetSymbolAddress(&pp, g_p);
    cudaGetSymbolAddress(&pwpt, g_WpT);
    cudaGetSymbolAddress(&ppreds, g_preds);
    cudaGetSymbolAddress(&pv, g_v);
    float* x1 = (float*)px1;
    float* x2 = (float*)px2;
    float* p  = (float*)pp;
    float* WpT = (float*)pwpt;
    float* preds = (float*)ppreds;
    float* v = (float*)pv;

    cudaFuncSetAttribute(routing_kernel,
                         cudaFuncAttributeMaxDynamicSharedMemorySize, RT_SMEM_BYTES);

    // 1) x1 = relu(features @ W1 + b1)     [4096,512]  TF32 tensor cores
    tf32gemm_kernel<true><<<dim3(H1/64, BATCH/128), 256>>>(
        features, W1, b1, x1, BATCH, H1, IN_DIM);

    // 2) x2 = relu(x1 @ W2 + b2)           [4096,256]  TF32
    tf32gemm_kernel<true><<<dim3(H2/64, BATCH/128), 256>>>(
        x1, W2, b2, x2, BATCH, H2, H1);

    // 3) WpT = transpose(Wp)
    transpose_wp_kernel<<<NPRIM*H2*PDIM/256, 256>>>(Wp, WpT);

    // 4) p = x2 @ WpT + bp                 [4096,256]  TF32
    tf32gemm_kernel<false><<<dim3(H2/64, BATCH/128), 256>>>(
        x2, WpT, bp, p, BATCH, H2, H2);

    // 5) per-capsule LayerNorm (in place)
    ln_kernel<<<BATCH*NPRIM/256, 256>>>(p, lg, lb);

    // 6) preds einsum
    preds_kernel<<<dim3(BATCH/128, NPRIM), 256>>>(p, Wr, preds);

    // 7) dynamic routing (3 iters, block-local) -> v
    routing_kernel<<<BATCH, 512, RT_SMEM_BYTES>>>(preds, v);

    // 8) logits = v.reshape(B,1600) @ Wc + bc   (fp32 for final precision)
    sgemm_kernel<32,128,8,2,8,false><<<dim3(1, BATCH/32), 256>>>(
        v, Wc, bc, out, BATCH, NLAB, JO);
}